// round 16
// baseline (speedup 1.0000x reference)
#include <cuda_runtime.h>
#include <cuda_fp16.h>
#include <math.h>
#include <stdint.h>

#define NN 50000
#define EE 800000
#define FIN 256
#define HD1 256   // H1*D = 8*32
#define H1 8
#define D1 32
#define C2 16
#define NB 196    // (NN+255)/256 scan blocks

#define BM 128
#define BN 128
#define KC 64
#define NKC (FIN / KC)               // 4 stages of K=64
#define NMT ((NN + BM - 1) / BM)     // 391 M tiles

// ---------------- scratch (static device globals; no allocation) ----------------
__device__ __half  g_h1[NN * HD1];   // x @ W1 (fp16; only consumed by agg1 gather)
__device__ float g_el1[NN * H1];     // exp(el1) — pre-exponentiated in gemm1 epilogue
__device__ __half g_h2[NN * C2];     // x1 @ W2 (fp16; consumed by agg2 gather)
__device__ float g_el2[NN];
__device__ float g_er2[NN];
__device__ int   g_deg[NN];
__device__ int   g_rowptr[NN + 1];
__device__ int   g_bsum[NB];
__device__ int   g_boff[NB];
__device__ int   g_eslot[EE];
__device__ int   g_esrc[EE];
__device__ __half g_Wh_t[FIN * HD1];  // W1^T fp16  [N][K]
__device__ __half g_xh[NN * FIN];     // x fp16

__device__ __forceinline__ float eluf(float x) {
    return x > 0.f ? x : expm1f(x);
}

// ---------------- cp.async helpers ----------------
__device__ __forceinline__ void cp16(uint32_t smem_dst, const void* gsrc, int src_bytes) {
    asm volatile("cp.async.cg.shared.global [%0], [%1], 16, %2;"
                 :: "r"(smem_dst), "l"(gsrc), "r"(src_bytes));
}
#define CP_COMMIT() asm volatile("cp.async.commit_group;" ::: "memory")
#define CP_WAIT0()  asm volatile("cp.async.wait_group 0;" ::: "memory")
#define CP_WAIT1()  asm volatile("cp.async.wait_group 1;" ::: "memory")
#define CP_WAIT3()  asm volatile("cp.async.wait_group 3;" ::: "memory")

// ---------------- W1 transpose -> fp16 ----------------
__global__ void convW_kernel(const float* __restrict__ W) {
    int id = blockIdx.x * blockDim.x + threadIdx.x;   // id = n*256 + k
    if (id >= FIN * HD1) return;
    int n = id >> 8, k = id & 255;
    g_Wh_t[id] = __float2half_rn(W[k * HD1 + n]);
}

// ---------------- x -> fp16 ----------------
__global__ void __launch_bounds__(256)
convX_kernel(const float* __restrict__ x) {
    int id = blockIdx.x * blockDim.x + threadIdx.x;   // one float4 per thread
    if (id >= NN * FIN / 4) return;
    float4 v = ((const float4*)x)[id];
    __half2 a = __floats2half2_rn(v.x, v.y);
    __half2 b = __floats2half2_rn(v.z, v.w);
    uint2 u;
    u.x = *(uint32_t*)&a;
    u.y = *(uint32_t*)&b;
    ((uint2*)g_xh)[id] = u;
}

// ---------------- GEMM1 via mma.sync fp16 (single product), fused el1 ----------------
__device__ __forceinline__ void mma16816(float* d, const uint32_t* a, const uint32_t* b) {
    asm volatile(
        "mma.sync.aligned.m16n8k16.row.col.f32.f16.f16.f32 "
        "{%0,%1,%2,%3}, {%4,%5,%6,%7}, {%8,%9}, {%0,%1,%2,%3};"
        : "+f"(d[0]), "+f"(d[1]), "+f"(d[2]), "+f"(d[3])
        : "r"(a[0]), "r"(a[1]), "r"(a[2]), "r"(a[3]), "r"(b[0]), "r"(b[1]));
}

#define ST 72   // smem row stride in halves (64 + 8 pad); 144B rows
#define ARR (128 * ST * 2)                 // 18432B per array
#define STG (2 * ARR)                      // AH, BH = 36864 per stage
#define SM_AH(s) ((s) * STG)
#define SM_BH(s) ((s) * STG + ARR)
#define SM_G1_BYTES (2 * STG)              // 73728

__global__ void __launch_bounds__(256, 2)
gemm1_mma_kernel(const float* __restrict__ al1) {
    extern __shared__ char sm[];
    uint32_t smb = (uint32_t)__cvta_generic_to_shared(sm);

    int tid = threadIdx.x;
    int wid = tid >> 5;
    int lane = tid & 31;
    int g = lane >> 2;       // group 0..7
    int tig = lane & 3;      // thread-in-group 0..3
    int wm = wid & 3;        // warp M index 0..3 (32 rows each)
    int wn = wid >> 2;       // warp N index 0..1 (64 cols each)

    int rowBase = blockIdx.y * BM;
    int colBase = blockIdx.x * BN;

    auto loadStage = [&](int kc, int s) {
        int k0 = kc * KC;
#pragma unroll
        for (int i = 0; i < 4; i++) {
            int c = tid + i * 256;          // 0..1023
            int r = c >> 3;                 // 0..127
            int j = c & 7;                  // 16B chunk in row
            uint32_t d = (uint32_t)(r * (ST * 2) + j * 16);
            int grow = rowBase + r;
            int sz = (grow < NN) ? 16 : 0;
            size_t aoff = (size_t)grow * FIN + k0 + j * 8;
            cp16(smb + SM_AH(s) + d, (const void*)&g_xh[aoff], sz);
            size_t boff = (size_t)(colBase + r) * FIN + k0 + j * 8;
            cp16(smb + SM_BH(s) + d, (const void*)&g_Wh_t[boff], 16);
        }
    };

    loadStage(0, 0);
    CP_COMMIT();
    loadStage(1, 1);
    CP_COMMIT();

    float acc[2][8][4];
#pragma unroll
    for (int a = 0; a < 2; a++)
#pragma unroll
        for (int b = 0; b < 8; b++)
#pragma unroll
            for (int c = 0; c < 4; c++) acc[a][b][c] = 0.f;

    for (int kc = 0; kc < NKC; kc++) {
        if (kc >= NKC - 2) { CP_WAIT0(); } else { CP_WAIT1(); }
        __syncthreads();

        int s = kc & 1;
        const __half* As_h = (const __half*)(sm + SM_AH(s));
        const __half* Bs_h = (const __half*)(sm + SM_BH(s));

#pragma unroll
        for (int ks = 0; ks < KC / 16; ks++) {
            int co = ks * 16 + tig * 2;
            uint32_t ah[2][4];
#pragma unroll
            for (int mt = 0; mt < 2; mt++) {
                int r = wm * 32 + mt * 16 + g;
                ah[mt][0] = *(uint32_t*)&As_h[r * ST + co];
                ah[mt][1] = *(uint32_t*)&As_h[(r + 8) * ST + co];
                ah[mt][2] = *(uint32_t*)&As_h[r * ST + co + 8];
                ah[mt][3] = *(uint32_t*)&As_h[(r + 8) * ST + co + 8];
            }
#pragma unroll
            for (int nt = 0; nt < 8; nt++) {
                int n = wn * 64 + nt * 8 + g;
                uint32_t bh[2];
                bh[0] = *(uint32_t*)&Bs_h[n * ST + co];
                bh[1] = *(uint32_t*)&Bs_h[n * ST + co + 8];
#pragma unroll
                for (int mt = 0; mt < 2; mt++)
                    mma16816(acc[mt][nt], ah[mt], bh);
            }
        }

        if (kc + 2 < NKC) {
            __syncthreads();
            loadStage(kc + 2, s);
            CP_COMMIT();
        }
    }

    // --- epilogue: store h1 (fp16), fused el1 -> store exp(el1) ---
    int head_base = blockIdx.x * 4 + wn * 2;
#pragma unroll
    for (int mt = 0; mt < 2; mt++) {
        int r0 = rowBase + wm * 32 + mt * 16 + g;
        int r1 = r0 + 8;
        float e0[2] = {0.f, 0.f}, e1[2] = {0.f, 0.f};
#pragma unroll
        for (int nt = 0; nt < 8; nt++) {
            int hl = nt >> 2;
            int inner = (nt & 3) * 8 + tig * 2;
            int head = head_base + hl;
            float w0 = __ldg(&al1[head * D1 + inner]);
            float w1 = __ldg(&al1[head * D1 + inner + 1]);
            e0[hl] = fmaf(acc[mt][nt][0], w0, fmaf(acc[mt][nt][1], w1, e0[hl]));
            e1[hl] = fmaf(acc[mt][nt][2], w0, fmaf(acc[mt][nt][3], w1, e1[hl]));
            int col = colBase + wn * 64 + nt * 8 + tig * 2;
            if (r0 < NN)
                *(__half2*)&g_h1[(size_t)r0 * HD1 + col] =
                    __floats2half2_rn(acc[mt][nt][0], acc[mt][nt][1]);
            if (r1 < NN)
                *(__half2*)&g_h1[(size_t)r1 * HD1 + col] =
                    __floats2half2_rn(acc[mt][nt][2], acc[mt][nt][3]);
        }
#pragma unroll
        for (int hl = 0; hl < 2; hl++) {
#pragma unroll
            for (int off = 1; off < 4; off <<= 1) {
                e0[hl] += __shfl_xor_sync(0xffffffffu, e0[hl], off);
                e1[hl] += __shfl_xor_sync(0xffffffffu, e1[hl], off);
            }
        }
        if (tig == 0) {
            if (r0 < NN) {
                g_el1[r0 * H1 + head_base + 0] = __expf(e0[0]);
                g_el1[r0 * H1 + head_base + 1] = __expf(e0[1]);
            }
            if (r1 < NN) {
                g_el1[r1 * H1 + head_base + 0] = __expf(e1[0]);
                g_el1[r1 * H1 + head_base + 1] = __expf(e1[1]);
            }
        }
    }
}

// ---------------- CSR build ----------------
__global__ void csr_zero_kernel() {
    int i = blockIdx.x * blockDim.x + threadIdx.x;
    if (i < NN) g_deg[i] = 0;
}

__global__ void csr_count_kernel(const int* __restrict__ dst) {
    int e = blockIdx.x * blockDim.x + threadIdx.x;
    if (e < EE) g_eslot[e] = atomicAdd(&g_deg[dst[e]], 1);
}

__global__ void __launch_bounds__(256)
scanA_kernel() {
    __shared__ int ws[8];
    int t = threadIdx.x, lane = t & 31, w = t >> 5;
    int i = blockIdx.x * 256 + t;
    int v = (i < NN) ? g_deg[i] : 0;
    int s = v;
#pragma unroll
    for (int off = 1; off < 32; off <<= 1) {
        int nv = __shfl_up_sync(0xffffffffu, s, off);
        if (lane >= off) s += nv;
    }
    if (lane == 31) ws[w] = s;
    __syncthreads();
    if (t == 0) {
        int run = 0;
#pragma unroll
        for (int j = 0; j < 8; j++) { int xx = ws[j]; ws[j] = run; run += xx; }
        g_bsum[blockIdx.x] = run;
    }
    __syncthreads();
    if (i < NN) g_rowptr[i] = s - v + ws[w];
}

__global__ void __launch_bounds__(256)
scanB_kernel() {
    __shared__ int ws[8];
    int t = threadIdx.x, lane = t & 31, w = t >> 5;
    int v = (t < NB) ? g_bsum[t] : 0;
    int s = v;
#pragma unroll
    for (int off = 1; off < 32; off <<= 1) {
        int nv = __shfl_up_sync(0xffffffffu, s, off);
        if (lane >= off) s += nv;
    }
    if (lane == 31) ws[w] = s;
    __syncthreads();
    if (t == 0) {
        int run = 0;
#pragma unroll
        for (int j = 0; j < 8; j++) { int xx = ws[j]; ws[j] = run; run += xx; }
    }
    __syncthreads();
    if (t < NB) g_boff[t] = s - v + ws[w];
    if (t == NB - 1) g_rowptr[NN] = s + ws[w];
}

__global__ void __launch_bounds__(256)
scanC_kernel() {
    int i = blockIdx.x * 256 + threadIdx.x;
    if (i < NN) g_rowptr[i] += g_boff[blockIdx.x];
}

__global__ void csr_scatter_kernel(const int* __restrict__ src, const int* __restrict__ dst) {
    int e = blockIdx.x * blockDim.x + threadIdx.x;
    if (e < EE) {
        int pos = g_rowptr[dst[e]] + g_eslot[e];
        g_esrc[pos] = src[e];
    }
}

// ---------------- fused layer-1 aggregation + layer-2 projection ----------------
// One warp per dst node; 4-stage cp.async gather pipeline into smem slots.
// Each lane cp.asyncs + reads back only ITS OWN 16B slice (no cross-lane sync).
// exp(el1) prefetched into a static 4-reg ring at issue time.
__global__ void __launch_bounds__(256)
agg1_kernel(const float* __restrict__ b1, const float* __restrict__ W2,
            const float* __restrict__ al2, const float* __restrict__ ar2) {
    __shared__ float Ws[256][17];
    __shared__ float xs[8][264];
    __shared__ float al2s[16], ar2s[16];
    __shared__ __align__(16) char gbuf[8][4][512];   // [warp][slot][512B edge row]
    int tid = threadIdx.x;
    for (int i = tid; i < 256 * 16; i += 256) Ws[i >> 4][i & 15] = W2[i];
    if (tid < 16) { al2s[tid] = al2[tid]; ar2s[tid] = ar2[tid]; }
    __syncthreads();

    int w = tid >> 5;
    int n = blockIdx.x * 8 + w;
    int lane = tid & 31;
    if (n >= NN) return;
    int beg = g_rowptr[n], end = g_rowptr[n + 1];

    int h = lane >> 2;
    int baseoff = lane * 8;
    uint32_t slot0 = (uint32_t)__cvta_generic_to_shared(&gbuf[w][0][0]) + (uint32_t)(lane * 16);

    float acc[8];
#pragma unroll
    for (int i = 0; i < 8; i++) acc[i] = 0.f;
    float sum = 0.f;
    float elr[4];

    // prologue: fill 4 slots (predicated issue, unconditional commit)
#pragma unroll
    for (int j = 0; j < 4; j++) {
        if (beg + j < end) {
            int s = __ldg(&g_esrc[beg + j]);
            cp16(slot0 + j * 512, (const void*)(g_h1 + (size_t)s * HD1 + baseoff), 16);
            elr[j] = __ldg(&g_el1[s * H1 + h]);
        }
        CP_COMMIT();
    }

    for (int i = beg; i < end; i += 4) {
#pragma unroll
        for (int j = 0; j < 4; j++) {
            if (i + j < end) {
                CP_WAIT3();          // own group for edge (i+j) complete
                uint32_t a0, a1, a2, a3;
                asm volatile("ld.shared.v4.u32 {%0,%1,%2,%3}, [%4];"
                             : "=r"(a0), "=r"(a1), "=r"(a2), "=r"(a3)
                             : "r"(slot0 + j * 512));
                float ex = elr[j];
                sum += ex;
                float2 f0 = __half22float2(*(__half2*)&a0);
                float2 f1 = __half22float2(*(__half2*)&a1);
                float2 f2 = __half22float2(*(__half2*)&a2);
                float2 f3 = __half22float2(*(__half2*)&a3);
                acc[0] = fmaf(ex, f0.x, acc[0]);
                acc[1] = fmaf(ex, f0.y, acc[1]);
                acc[2] = fmaf(ex, f1.x, acc[2]);
                acc[3] = fmaf(ex, f1.y, acc[3]);
                acc[4] = fmaf(ex, f2.x, acc[4]);
                acc[5] = fmaf(ex, f2.y, acc[5]);
                acc[6] = fmaf(ex, f3.x, acc[6]);
                acc[7] = fmaf(ex, f3.y, acc[7]);
                int nx = i + j + 4;
                if (nx < end) {
                    int s = __ldg(&g_esrc[nx]);
                    cp16(slot0 + j * 512, (const void*)(g_h1 + (size_t)s * HD1 + baseoff), 16);
                    elr[j] = __ldg(&g_el1[s * H1 + h]);
                }
            }
            CP_COMMIT();
        }
    }

    float inv = (end > beg) ? 1.f / sum : 0.f;
    float4 bb0 = *(const float4*)&b1[baseoff];
    float4 bb1 = *(const float4*)&b1[baseoff + 4];
    float4 v0, v1;
    v0.x = eluf(acc[0] * inv + bb0.x);
    v0.y = eluf(acc[1] * inv + bb0.y);
    v0.z = eluf(acc[2] * inv + bb0.z);
    v0.w = eluf(acc[3] * inv + bb0.w);
    v1.x = eluf(acc[4] * inv + bb1.x);
    v1.y = eluf(acc[5] * inv + bb1.y);
    v1.z = eluf(acc[6] * inv + bb1.z);
    v1.w = eluf(acc[7] * inv + bb1.w);
    *(float4*)&xs[w][baseoff] = v0;
    *(float4*)&xs[w][baseoff + 4] = v1;
    __syncwarp();

    // --- fused gemm2: h2[n] = x1[n] @ W2 (fp16 store); el2/er2 ---
    int c = lane & 15, half = lane >> 4;
    const float* xr = xs[w];
    float a0 = 0.f, a1 = 0.f;
    int kbase = half * 128;
#pragma unroll 4
    for (int k = 0; k < 128; k += 2) {
        a0 = fmaf(xr[kbase + k], Ws[kbase + k][c], a0);
        a1 = fmaf(xr[kbase + k + 1], Ws[kbase + k + 1][c], a1);
    }
    float hv = a0 + a1;
    hv += __shfl_xor_sync(0xffffffffu, hv, 16);
    if (lane < 16) g_h2[n * C2 + c] = __float2half_rn(hv);
    float pl = (lane < 16) ? hv * al2s[c] : 0.f;
    float pr = (lane < 16) ? hv * ar2s[c] : 0.f;
#pragma unroll
    for (int off = 16; off; off >>= 1) {
        pl += __shfl_xor_sync(0xffffffffu, pl, off);
        pr += __shfl_xor_sync(0xffffffffu, pr, off);
    }
    if (lane == 0) { g_el2[n] = pl; g_er2[n] = pr; }
}

// ---------------- layer-2 aggregation + final ELU -> d_out ----------------
__global__ void __launch_bounds__(256, 6)
agg2_kernel(const float* __restrict__ b2, float* __restrict__ out) {
    int n = blockIdx.x * 8 + (threadIdx.x >> 5);
    int lane = threadIdx.x & 31;
    if (n >= NN) return;
    int beg = g_rowptr[n], end = g_rowptr[n + 1];
    float ern = g_er2[n];

    int c = lane & 15, half = lane >> 4;
    float acc = 0.f, sum = 0.f;
    int i = beg + half;
    for (; i + 6 < end; i += 8) {
        int idx[4];
#pragma unroll
        for (int j = 0; j < 4; j++) idx[j] = __ldg(&g_esrc[i + j * 2]);
#pragma unroll
        for (int j = 0; j < 4; j++) {
            int s = idx[j];
            float e = g_el2[s] + ern;
            e = e > 0.f ? e : 0.2f * e;
            float ex = __expf(e);
            sum += ex;
            acc = fmaf(ex, __half2float(g_h2[s * C2 + c]), acc);
        }
    }
    for (; i < end; i += 2) {
        int s = __ldg(&g_esrc[i]);
        float e = g_el2[s] + ern;
        e = e > 0.f ? e : 0.2f * e;
        float ex = __expf(e);
        sum += ex;
        acc = fmaf(ex, __half2float(g_h2[s * C2 + c]), acc);
    }
    acc += __shfl_xor_sync(0xffffffffu, acc, 16);
    sum += __shfl_xor_sync(0xffffffffu, sum, 16);
    float inv = (end > beg) ? 1.f / sum : 0.f;
    float o = acc * inv + b2[c];
    o = o > 0.f ? o : expm1f(o);
    if (lane < 16) out[n * C2 + c] = o;
}

// ---------------- launch ----------------
extern "C" void kernel_launch(void* const* d_in, const int* in_sizes, int n_in,
                              void* d_out, int out_size) {
    const float* x   = (const float*)d_in[0];
    const int*   src = (const int*)d_in[1];
    const int*   dst = (const int*)d_in[2];
    const float* W1  = (const float*)d_in[3];
    const float* al1 = (const float*)d_in[4];
    const float* b1  = (const float*)d_in[6];
    const float* W2  = (const float*)d_in[7];
    const float* al2 = (const float*)d_in[8];
    const float* ar2 = (const float*)d_in[9];
    const float* b2  = (const float*)d_in[10];
    float* out = (float*)d_out;

    static cudaStream_t s1 = nullptr;
    static cudaEvent_t evF = nullptr, evJ = nullptr;
    if (!s1) {
        cudaFuncSetAttribute(gemm1_mma_kernel,
                             cudaFuncAttributeMaxDynamicSharedMemorySize, SM_G1_BYTES);
        cudaStreamCreateWithFlags(&s1, cudaStreamNonBlocking);
        cudaEventCreateWithFlags(&evF, cudaEventDisableTiming);
        cudaEventCreateWithFlags(&evJ, cudaEventDisableTiming);
    }

    // fork: side stream handles CSR chain in parallel with conv+gemm
    cudaEventRecord(evF, 0);
    cudaStreamWaitEvent(s1, evF, 0);

    convX_kernel<<<(NN * FIN / 4 + 255) / 256, 256>>>(x);                // main
    convW_kernel<<<(FIN * HD1 + 255) / 256, 256>>>(W1);                  // main
    csr_zero_kernel<<<(NN + 255) / 256, 256, 0, s1>>>();                 // side
    dim3 g1(2, NMT);
    gemm1_mma_kernel<<<g1, 256, SM_G1_BYTES>>>(al1);                     // main (4th: profiled)
    csr_count_kernel<<<(EE + 255) / 256, 256, 0, s1>>>(dst);             // side
    scanA_kernel<<<NB, 256, 0, s1>>>();                                  // side
    scanB_kernel<<<1, 256, 0, s1>>>();                                   // side
    scanC_kernel<<<NB, 256, 0, s1>>>();                                  // side
    csr_scatter_kernel<<<(EE + 255) / 256, 256, 0, s1>>>(src, dst);      // side

    // join: aggregation needs both branches
    cudaEventRecord(evJ, s1);
    cudaStreamWaitEvent(0, evJ, 0);

    agg1_kernel<<<(NN + 7) / 8, 256>>>(b1, W2, al2, ar2);
    agg2_kernel<<<(NN + 7) / 8, 256>>>(b2, out);
}

// round 17
// speedup vs baseline: 1.2123x; 1.2123x over previous
#include <cuda_runtime.h>
#include <cuda_fp16.h>
#include <math.h>
#include <stdint.h>

#define NN 50000
#define EE 800000
#define FIN 256
#define HD1 256   // H1*D = 8*32
#define H1 8
#define D1 32
#define C2 16
#define NB 196    // (NN+255)/256 scan blocks

#define BM 128
#define BN 128
#define KC 64
#define NKC (FIN / KC)               // 4 stages of K=64
#define NMT ((NN + BM - 1) / BM)     // 391 M tiles

// ---------------- scratch (static device globals; no allocation) ----------------
__device__ __half  g_h1[NN * HD1];   // x @ W1 (fp16; only consumed by agg1 gather)
__device__ float g_el1[NN * H1];     // exp(el1) — pre-exponentiated in gemm1 epilogue
__device__ __half g_h2[NN * C2];     // x1 @ W2 (fp16; consumed by agg2 gather)
__device__ float g_el2[NN];
__device__ float g_er2[NN];
__device__ int   g_deg[NN];
__device__ int   g_rowptr[NN + 1];
__device__ int   g_bsum[NB];
__device__ int   g_boff[NB];
__device__ int   g_eslot[EE];
__device__ int   g_esrc[EE];
__device__ __half g_Wh_t[FIN * HD1];  // W1^T fp16  [N][K]
__device__ __half g_xh[NN * FIN];     // x fp16

__device__ __forceinline__ float eluf(float x) {
    return x > 0.f ? x : expm1f(x);
}

// ---------------- cp.async helpers ----------------
__device__ __forceinline__ void cp16(uint32_t smem_dst, const void* gsrc, int src_bytes) {
    asm volatile("cp.async.cg.shared.global [%0], [%1], 16, %2;"
                 :: "r"(smem_dst), "l"(gsrc), "r"(src_bytes));
}
#define CP_COMMIT() asm volatile("cp.async.commit_group;" ::: "memory")
#define CP_WAIT0()  asm volatile("cp.async.wait_group 0;" ::: "memory")
#define CP_WAIT1()  asm volatile("cp.async.wait_group 1;" ::: "memory")

// ---------------- W1 transpose -> fp16 ----------------
__global__ void convW_kernel(const float* __restrict__ W) {
    int id = blockIdx.x * blockDim.x + threadIdx.x;   // id = n*256 + k
    if (id >= FIN * HD1) return;
    int n = id >> 8, k = id & 255;
    g_Wh_t[id] = __float2half_rn(W[k * HD1 + n]);
}

// ---------------- x -> fp16 ----------------
__global__ void __launch_bounds__(256)
convX_kernel(const float* __restrict__ x) {
    int id = blockIdx.x * blockDim.x + threadIdx.x;   // one float4 per thread
    if (id >= NN * FIN / 4) return;
    float4 v = ((const float4*)x)[id];
    __half2 a = __floats2half2_rn(v.x, v.y);
    __half2 b = __floats2half2_rn(v.z, v.w);
    uint2 u;
    u.x = *(uint32_t*)&a;
    u.y = *(uint32_t*)&b;
    ((uint2*)g_xh)[id] = u;
}

// ---------------- GEMM1 via mma.sync fp16 (single product), fused el1 ----------------
__device__ __forceinline__ void mma16816(float* d, const uint32_t* a, const uint32_t* b) {
    asm volatile(
        "mma.sync.aligned.m16n8k16.row.col.f32.f16.f16.f32 "
        "{%0,%1,%2,%3}, {%4,%5,%6,%7}, {%8,%9}, {%0,%1,%2,%3};"
        : "+f"(d[0]), "+f"(d[1]), "+f"(d[2]), "+f"(d[3])
        : "r"(a[0]), "r"(a[1]), "r"(a[2]), "r"(a[3]), "r"(b[0]), "r"(b[1]));
}

#define ST 72   // smem row stride in halves (64 + 8 pad); 144B rows
#define ARR (128 * ST * 2)                 // 18432B per array
#define STG (2 * ARR)                      // AH, BH = 36864 per stage
#define SM_AH(s) ((s) * STG)
#define SM_BH(s) ((s) * STG + ARR)
#define SM_G1_BYTES (2 * STG)              // 73728

__global__ void __launch_bounds__(256, 2)
gemm1_mma_kernel(const float* __restrict__ al1) {
    extern __shared__ char sm[];
    uint32_t smb = (uint32_t)__cvta_generic_to_shared(sm);

    int tid = threadIdx.x;
    int wid = tid >> 5;
    int lane = tid & 31;
    int g = lane >> 2;       // group 0..7
    int tig = lane & 3;      // thread-in-group 0..3
    int wm = wid & 3;        // warp M index 0..3 (32 rows each)
    int wn = wid >> 2;       // warp N index 0..1 (64 cols each)

    int rowBase = blockIdx.y * BM;
    int colBase = blockIdx.x * BN;

    auto loadStage = [&](int kc, int s) {
        int k0 = kc * KC;
#pragma unroll
        for (int i = 0; i < 4; i++) {
            int c = tid + i * 256;          // 0..1023
            int r = c >> 3;                 // 0..127
            int j = c & 7;                  // 16B chunk in row
            uint32_t d = (uint32_t)(r * (ST * 2) + j * 16);
            int grow = rowBase + r;
            int sz = (grow < NN) ? 16 : 0;
            size_t aoff = (size_t)grow * FIN + k0 + j * 8;
            cp16(smb + SM_AH(s) + d, (const void*)&g_xh[aoff], sz);
            size_t boff = (size_t)(colBase + r) * FIN + k0 + j * 8;
            cp16(smb + SM_BH(s) + d, (const void*)&g_Wh_t[boff], 16);
        }
    };

    loadStage(0, 0);
    CP_COMMIT();
    loadStage(1, 1);
    CP_COMMIT();

    float acc[2][8][4];
#pragma unroll
    for (int a = 0; a < 2; a++)
#pragma unroll
        for (int b = 0; b < 8; b++)
#pragma unroll
            for (int c = 0; c < 4; c++) acc[a][b][c] = 0.f;

    for (int kc = 0; kc < NKC; kc++) {
        if (kc >= NKC - 2) { CP_WAIT0(); } else { CP_WAIT1(); }
        __syncthreads();

        int s = kc & 1;
        const __half* As_h = (const __half*)(sm + SM_AH(s));
        const __half* Bs_h = (const __half*)(sm + SM_BH(s));

#pragma unroll
        for (int ks = 0; ks < KC / 16; ks++) {
            int co = ks * 16 + tig * 2;
            uint32_t ah[2][4];
#pragma unroll
            for (int mt = 0; mt < 2; mt++) {
                int r = wm * 32 + mt * 16 + g;
                ah[mt][0] = *(uint32_t*)&As_h[r * ST + co];
                ah[mt][1] = *(uint32_t*)&As_h[(r + 8) * ST + co];
                ah[mt][2] = *(uint32_t*)&As_h[r * ST + co + 8];
                ah[mt][3] = *(uint32_t*)&As_h[(r + 8) * ST + co + 8];
            }
#pragma unroll
            for (int nt = 0; nt < 8; nt++) {
                int n = wn * 64 + nt * 8 + g;
                uint32_t bh[2];
                bh[0] = *(uint32_t*)&Bs_h[n * ST + co];
                bh[1] = *(uint32_t*)&Bs_h[n * ST + co + 8];
#pragma unroll
                for (int mt = 0; mt < 2; mt++)
                    mma16816(acc[mt][nt], ah[mt], bh);
            }
        }

        if (kc + 2 < NKC) {
            __syncthreads();
            loadStage(kc + 2, s);
            CP_COMMIT();
        }
    }

    // --- epilogue: store h1 (fp16), fused el1 -> store exp(el1) ---
    int head_base = blockIdx.x * 4 + wn * 2;
#pragma unroll
    for (int mt = 0; mt < 2; mt++) {
        int r0 = rowBase + wm * 32 + mt * 16 + g;
        int r1 = r0 + 8;
        float e0[2] = {0.f, 0.f}, e1[2] = {0.f, 0.f};
#pragma unroll
        for (int nt = 0; nt < 8; nt++) {
            int hl = nt >> 2;
            int inner = (nt & 3) * 8 + tig * 2;
            int head = head_base + hl;
            float w0 = __ldg(&al1[head * D1 + inner]);
            float w1 = __ldg(&al1[head * D1 + inner + 1]);
            e0[hl] = fmaf(acc[mt][nt][0], w0, fmaf(acc[mt][nt][1], w1, e0[hl]));
            e1[hl] = fmaf(acc[mt][nt][2], w0, fmaf(acc[mt][nt][3], w1, e1[hl]));
            int col = colBase + wn * 64 + nt * 8 + tig * 2;
            if (r0 < NN)
                *(__half2*)&g_h1[(size_t)r0 * HD1 + col] =
                    __floats2half2_rn(acc[mt][nt][0], acc[mt][nt][1]);
            if (r1 < NN)
                *(__half2*)&g_h1[(size_t)r1 * HD1 + col] =
                    __floats2half2_rn(acc[mt][nt][2], acc[mt][nt][3]);
        }
#pragma unroll
        for (int hl = 0; hl < 2; hl++) {
#pragma unroll
            for (int off = 1; off < 4; off <<= 1) {
                e0[hl] += __shfl_xor_sync(0xffffffffu, e0[hl], off);
                e1[hl] += __shfl_xor_sync(0xffffffffu, e1[hl], off);
            }
        }
        if (tig == 0) {
            if (r0 < NN) {
                g_el1[r0 * H1 + head_base + 0] = __expf(e0[0]);
                g_el1[r0 * H1 + head_base + 1] = __expf(e0[1]);
            }
            if (r1 < NN) {
                g_el1[r1 * H1 + head_base + 0] = __expf(e1[0]);
                g_el1[r1 * H1 + head_base + 1] = __expf(e1[1]);
            }
        }
    }
}

// ---------------- CSR build ----------------
__global__ void csr_zero_kernel() {
    int i = blockIdx.x * blockDim.x + threadIdx.x;
    if (i < NN) g_deg[i] = 0;
}

__global__ void csr_count_kernel(const int* __restrict__ dst) {
    int e = blockIdx.x * blockDim.x + threadIdx.x;
    if (e < EE) g_eslot[e] = atomicAdd(&g_deg[dst[e]], 1);
}

__global__ void __launch_bounds__(256)
scanA_kernel() {
    __shared__ int ws[8];
    int t = threadIdx.x, lane = t & 31, w = t >> 5;
    int i = blockIdx.x * 256 + t;
    int v = (i < NN) ? g_deg[i] : 0;
    int s = v;
#pragma unroll
    for (int off = 1; off < 32; off <<= 1) {
        int nv = __shfl_up_sync(0xffffffffu, s, off);
        if (lane >= off) s += nv;
    }
    if (lane == 31) ws[w] = s;
    __syncthreads();
    if (t == 0) {
        int run = 0;
#pragma unroll
        for (int j = 0; j < 8; j++) { int xx = ws[j]; ws[j] = run; run += xx; }
        g_bsum[blockIdx.x] = run;
    }
    __syncthreads();
    if (i < NN) g_rowptr[i] = s - v + ws[w];
}

__global__ void __launch_bounds__(256)
scanB_kernel() {
    __shared__ int ws[8];
    int t = threadIdx.x, lane = t & 31, w = t >> 5;
    int v = (t < NB) ? g_bsum[t] : 0;
    int s = v;
#pragma unroll
    for (int off = 1; off < 32; off <<= 1) {
        int nv = __shfl_up_sync(0xffffffffu, s, off);
        if (lane >= off) s += nv;
    }
    if (lane == 31) ws[w] = s;
    __syncthreads();
    if (t == 0) {
        int run = 0;
#pragma unroll
        for (int j = 0; j < 8; j++) { int xx = ws[j]; ws[j] = run; run += xx; }
    }
    __syncthreads();
    if (t < NB) g_boff[t] = s - v + ws[w];
    if (t == NB - 1) g_rowptr[NN] = s + ws[w];
}

__global__ void __launch_bounds__(256)
scanC_kernel() {
    int i = blockIdx.x * 256 + threadIdx.x;
    if (i < NN) g_rowptr[i] += g_boff[blockIdx.x];
}

__global__ void csr_scatter_kernel(const int* __restrict__ src, const int* __restrict__ dst) {
    int e = blockIdx.x * blockDim.x + threadIdx.x;
    if (e < EE) {
        int pos = g_rowptr[dst[e]] + g_eslot[e];
        g_esrc[pos] = src[e];
    }
}

// ---------------- fused layer-1 aggregation + layer-2 projection ----------------
// One warp per dst node; 8-deep index prefetch (r13 form); W2/al2/ar2 read via
// __ldg (L1-resident 16KB) — no Ws smem, no block-start fill/sync.
__global__ void __launch_bounds__(256)
agg1_kernel(const float* __restrict__ b1, const float* __restrict__ W2,
            const float* __restrict__ al2, const float* __restrict__ ar2) {
    __shared__ float xs[8][264];
    int tid = threadIdx.x;
    int w = tid >> 5;
    int n = blockIdx.x * 8 + w;
    int lane = tid & 31;
    if (n >= NN) return;
    int beg = g_rowptr[n], end = g_rowptr[n + 1];

    int h = lane >> 2;
    int baseoff = lane * 8;
    float acc[8];
#pragma unroll
    for (int i = 0; i < 8; i++) acc[i] = 0.f;
    float sum = 0.f;

    int i = beg;
    for (; i + 8 <= end; i += 8) {
        int idx[8];
#pragma unroll
        for (int j = 0; j < 8; j++) idx[j] = __ldg(&g_esrc[i + j]);
#pragma unroll
        for (int j = 0; j < 8; j++) {
            int s = idx[j];
            float ex = g_el1[s * H1 + h];           // pre-exponentiated
            sum += ex;
            uint4 u = *(const uint4*)(g_h1 + (size_t)s * HD1 + baseoff);
            float2 f0 = __half22float2(*(__half2*)&u.x);
            float2 f1 = __half22float2(*(__half2*)&u.y);
            float2 f2 = __half22float2(*(__half2*)&u.z);
            float2 f3 = __half22float2(*(__half2*)&u.w);
            acc[0] = fmaf(ex, f0.x, acc[0]);
            acc[1] = fmaf(ex, f0.y, acc[1]);
            acc[2] = fmaf(ex, f1.x, acc[2]);
            acc[3] = fmaf(ex, f1.y, acc[3]);
            acc[4] = fmaf(ex, f2.x, acc[4]);
            acc[5] = fmaf(ex, f2.y, acc[5]);
            acc[6] = fmaf(ex, f3.x, acc[6]);
            acc[7] = fmaf(ex, f3.y, acc[7]);
        }
    }
    for (; i < end; ++i) {
        int s = __ldg(&g_esrc[i]);
        float ex = g_el1[s * H1 + h];
        sum += ex;
        uint4 u = *(const uint4*)(g_h1 + (size_t)s * HD1 + baseoff);
        float2 f0 = __half22float2(*(__half2*)&u.x);
        float2 f1 = __half22float2(*(__half2*)&u.y);
        float2 f2 = __half22float2(*(__half2*)&u.z);
        float2 f3 = __half22float2(*(__half2*)&u.w);
        acc[0] = fmaf(ex, f0.x, acc[0]);
        acc[1] = fmaf(ex, f0.y, acc[1]);
        acc[2] = fmaf(ex, f1.x, acc[2]);
        acc[3] = fmaf(ex, f1.y, acc[3]);
        acc[4] = fmaf(ex, f2.x, acc[4]);
        acc[5] = fmaf(ex, f2.y, acc[5]);
        acc[6] = fmaf(ex, f3.x, acc[6]);
        acc[7] = fmaf(ex, f3.y, acc[7]);
    }

    float inv = (end > beg) ? 1.f / sum : 0.f;
    float4 bb0 = *(const float4*)&b1[baseoff];
    float4 bb1 = *(const float4*)&b1[baseoff + 4];
    float4 v0, v1;
    v0.x = eluf(acc[0] * inv + bb0.x);
    v0.y = eluf(acc[1] * inv + bb0.y);
    v0.z = eluf(acc[2] * inv + bb0.z);
    v0.w = eluf(acc[3] * inv + bb0.w);
    v1.x = eluf(acc[4] * inv + bb1.x);
    v1.y = eluf(acc[5] * inv + bb1.y);
    v1.z = eluf(acc[6] * inv + bb1.z);
    v1.w = eluf(acc[7] * inv + bb1.w);
    *(float4*)&xs[w][baseoff] = v0;
    *(float4*)&xs[w][baseoff + 4] = v1;
    __syncwarp();

    // --- fused gemm2: h2[n] = x1[n] @ W2 (W2 via __ldg, L1-resident) ---
    int c = lane & 15, half = lane >> 4;
    const float* xr = xs[w];
    float a0 = 0.f, a1 = 0.f;
    int kbase = half * 128;
#pragma unroll 4
    for (int k = 0; k < 128; k += 2) {
        a0 = fmaf(xr[kbase + k], __ldg(&W2[(kbase + k) * C2 + c]), a0);
        a1 = fmaf(xr[kbase + k + 1], __ldg(&W2[(kbase + k + 1) * C2 + c]), a1);
    }
    float hv = a0 + a1;
    hv += __shfl_xor_sync(0xffffffffu, hv, 16);
    if (lane < 16) g_h2[n * C2 + c] = __float2half_rn(hv);
    float pl = (lane < 16) ? hv * __ldg(&al2[c]) : 0.f;
    float pr = (lane < 16) ? hv * __ldg(&ar2[c]) : 0.f;
#pragma unroll
    for (int off = 16; off; off >>= 1) {
        pl += __shfl_xor_sync(0xffffffffu, pl, off);
        pr += __shfl_xor_sync(0xffffffffu, pr, off);
    }
    if (lane == 0) { g_el2[n] = pl; g_er2[n] = pr; }
}

// ---------------- layer-2 aggregation + final ELU -> d_out ----------------
__global__ void __launch_bounds__(256, 6)
agg2_kernel(const float* __restrict__ b2, float* __restrict__ out) {
    int n = blockIdx.x * 8 + (threadIdx.x >> 5);
    int lane = threadIdx.x & 31;
    if (n >= NN) return;
    int beg = g_rowptr[n], end = g_rowptr[n + 1];
    float ern = g_er2[n];

    int c = lane & 15, half = lane >> 4;
    float acc = 0.f, sum = 0.f;
    int i = beg + half;
    for (; i + 6 < end; i += 8) {
        int idx[4];
#pragma unroll
        for (int j = 0; j < 4; j++) idx[j] = __ldg(&g_esrc[i + j * 2]);
#pragma unroll
        for (int j = 0; j < 4; j++) {
            int s = idx[j];
            float e = g_el2[s] + ern;
            e = e > 0.f ? e : 0.2f * e;
            float ex = __expf(e);
            sum += ex;
            acc = fmaf(ex, __half2float(g_h2[s * C2 + c]), acc);
        }
    }
    for (; i < end; i += 2) {
        int s = __ldg(&g_esrc[i]);
        float e = g_el2[s] + ern;
        e = e > 0.f ? e : 0.2f * e;
        float ex = __expf(e);
        sum += ex;
        acc = fmaf(ex, __half2float(g_h2[s * C2 + c]), acc);
    }
    acc += __shfl_xor_sync(0xffffffffu, acc, 16);
    sum += __shfl_xor_sync(0xffffffffu, sum, 16);
    float inv = (end > beg) ? 1.f / sum : 0.f;
    float o = acc * inv + b2[c];
    o = o > 0.f ? o : expm1f(o);
    if (lane < 16) out[n * C2 + c] = o;
}

// ---------------- launch ----------------
extern "C" void kernel_launch(void* const* d_in, const int* in_sizes, int n_in,
                              void* d_out, int out_size) {
    const float* x   = (const float*)d_in[0];
    const int*   src = (const int*)d_in[1];
    const int*   dst = (const int*)d_in[2];
    const float* W1  = (const float*)d_in[3];
    const float* al1 = (const float*)d_in[4];
    const float* b1  = (const float*)d_in[6];
    const float* W2  = (const float*)d_in[7];
    const float* al2 = (const float*)d_in[8];
    const float* ar2 = (const float*)d_in[9];
    const float* b2  = (const float*)d_in[10];
    float* out = (float*)d_out;

    static cudaStream_t s1 = nullptr;
    static cudaEvent_t evF = nullptr, evJ = nullptr;
    if (!s1) {
        cudaFuncSetAttribute(gemm1_mma_kernel,
                             cudaFuncAttributeMaxDynamicSharedMemorySize, SM_G1_BYTES);
        cudaStreamCreateWithFlags(&s1, cudaStreamNonBlocking);
        cudaEventCreateWithFlags(&evF, cudaEventDisableTiming);
        cudaEventCreateWithFlags(&evJ, cudaEventDisableTiming);
    }

    // fork: side stream handles CSR chain in parallel with conv+gemm
    cudaEventRecord(evF, 0);
    cudaStreamWaitEvent(s1, evF, 0);

    convX_kernel<<<(NN * FIN / 4 + 255) / 256, 256>>>(x);                // main
    convW_kernel<<<(FIN * HD1 + 255) / 256, 256>>>(W1);                  // main
    csr_zero_kernel<<<(NN + 255) / 256, 256, 0, s1>>>();                 // side
    dim3 g1(2, NMT);
    gemm1_mma_kernel<<<g1, 256, SM_G1_BYTES>>>(al1);                     // main (4th: profiled)
    csr_count_kernel<<<(EE + 255) / 256, 256, 0, s1>>>(dst);             // side
    scanA_kernel<<<NB, 256, 0, s1>>>();                                  // side
    scanB_kernel<<<1, 256, 0, s1>>>();                                   // side
    scanC_kernel<<<NB, 256, 0, s1>>>();                                  // side
    csr_scatter_kernel<<<(EE + 255) / 256, 256, 0, s1>>>(src, dst);      // side

    // join: aggregation needs both branches
    cudaEventRecord(evJ, s1);
    cudaStreamWaitEvent(0, evJ, 0);

    agg1_kernel<<<(NN + 7) / 8, 256>>>(b1, W2, al2, ar2);
    agg2_kernel<<<(NN + 7) / 8, 256>>>(b2, out);
}